// round 1
// baseline (speedup 1.0000x reference)
#include <cuda_runtime.h>
#include <cuda_bf16.h>
#include <math.h>

// ---------------- problem constants ----------------
#define B_      32
#define HW_     56
#define L_      3136            // 56*56
#define C_      384
#define NH_     12
#define HD_     32
#define WS_     7
#define NTOK_   49              // WS*WS
#define NWIN_   64              // (56/7)^2 per image
#define BN_     2048            // B_*NWIN_
#define MTOT_   100352          // BN_*NTOK_ == B_*L_
#define HID_    1536
#define QKVN_   1152
#define SHIFT_  3
#define SCALE_  0.17677669529663687f   // 1/sqrt(32)

// ---------------- scratch (device globals; no allocs) ----------------
__device__ float g_win[(size_t)MTOT_ * C_];       // LN1 + shifted windows
__device__ float g_qkv[(size_t)MTOT_ * QKVN_];    // qkv projection
__device__ float g_att[(size_t)MTOT_ * C_];       // attention output (window order)
__device__ float g_x1 [(size_t)MTOT_ * C_];       // residual1 + proj (original order)
__device__ float g_h2 [(size_t)MTOT_ * C_];       // LN2 output
__device__ float g_hid[(size_t)MTOT_ * HID_];     // fc1+gelu output

// map window-order row r -> original-layout row index (roll+window reverse)
__device__ __forceinline__ int win_row_to_orig(int r) {
    int bn = r / NTOK_, n = r - bn * NTOK_;
    int b  = bn >> 6,  wi = bn & 63;
    int i = n / WS_, j = n - i * WS_;
    int h = (wi >> 3) * WS_ + i + SHIFT_; if (h >= HW_) h -= HW_;
    int w = (wi & 7)  * WS_ + j + SHIFT_; if (w >= HW_) w -= HW_;
    return b * L_ + h * HW_ + w;
}

// ---------------- LayerNorm kernels ----------------
// one block (128 thr) per output row; 3 elems/thread
template<bool SHIFT_WINDOW>
__global__ __launch_bounds__(128) void ln_kernel(const float* __restrict__ x,
                                                 const float* __restrict__ g,
                                                 const float* __restrict__ b,
                                                 float* __restrict__ out)
{
    int r = blockIdx.x;
    int src_row = SHIFT_WINDOW ? win_row_to_orig(r) : r;
    const float* src = x + (size_t)src_row * C_;
    int t = threadIdx.x;

    float v[3], s = 0.f, s2 = 0.f;
#pragma unroll
    for (int l = 0; l < 3; ++l) {
        v[l] = src[t + l * 128];
        s += v[l]; s2 += v[l] * v[l];
    }
    // block reduce (4 warps)
    __shared__ float red[8];
#pragma unroll
    for (int o = 16; o > 0; o >>= 1) {
        s  += __shfl_down_sync(0xffffffffu, s,  o);
        s2 += __shfl_down_sync(0xffffffffu, s2, o);
    }
    int lane = t & 31, wid = t >> 5;
    if (lane == 0) { red[wid] = s; red[4 + wid] = s2; }
    __syncthreads();
    s  = red[0] + red[1] + red[2] + red[3];
    s2 = red[4] + red[5] + red[6] + red[7];
    float mean = s * (1.f / C_);
    float var  = s2 * (1.f / C_) - mean * mean;
    float inv  = rsqrtf(var + 1e-5f);

    float* dst = out + (size_t)r * C_;
#pragma unroll
    for (int l = 0; l < 3; ++l) {
        int c = t + l * 128;
        dst[c] = (v[l] - mean) * inv * g[c] + b[c];
    }
}

// ---------------- GEMM (fp32, 128x128x16, 256 thr, 8x8/thread) ----------------
// epilogues: 0 = +bias ; 1 = +bias,gelu ; 2 = +bias, window-reverse + residual(Res, orig order)
//            3 = +bias + residual(Res, same order) -> Out
#define BM 128
#define BN 128
#define BK 16

template<int EPI>
__global__ __launch_bounds__(256) void gemm_kernel(const float* __restrict__ A,
                                                   const float* __restrict__ Bm,
                                                   const float* __restrict__ bias,
                                                   const float* __restrict__ Res,
                                                   float* __restrict__ Out,
                                                   int M, int N, int K)
{
    __shared__ float As[BK][BM];
    __shared__ float Bs[BK][BN];

    int tid = threadIdx.x;
    int bx = blockIdx.x, by = blockIdx.y;
    const float* Ab = A  + (size_t)by * BM * K;
    const float* Bb = Bm + (size_t)bx * BN;

    int arow = tid >> 2, acol = (tid & 3) * 4;   // A tile: rows {arow, arow+64}, cols acol..+3
    int brow = tid >> 5, bcol = (tid & 31) * 4;  // B tile: rows {brow, brow+8}
    int tx = tid & 15, ty = tid >> 4;

    float acc[8][8];
#pragma unroll
    for (int i = 0; i < 8; ++i)
#pragma unroll
        for (int j = 0; j < 8; ++j) acc[i][j] = 0.f;

    for (int k0 = 0; k0 < K; k0 += BK) {
        float4 a0 = *(const float4*)(Ab + (size_t)arow        * K + k0 + acol);
        float4 a1 = *(const float4*)(Ab + (size_t)(arow + 64) * K + k0 + acol);
        float4 b0 = *(const float4*)(Bb + (size_t)(k0 + brow)     * N + bcol);
        float4 b1 = *(const float4*)(Bb + (size_t)(k0 + brow + 8) * N + bcol);
        __syncthreads();
        As[acol + 0][arow] = a0.x; As[acol + 1][arow] = a0.y;
        As[acol + 2][arow] = a0.z; As[acol + 3][arow] = a0.w;
        As[acol + 0][arow + 64] = a1.x; As[acol + 1][arow + 64] = a1.y;
        As[acol + 2][arow + 64] = a1.z; As[acol + 3][arow + 64] = a1.w;
        *(float4*)&Bs[brow][bcol]     = b0;
        *(float4*)&Bs[brow + 8][bcol] = b1;
        __syncthreads();
#pragma unroll
        for (int kk = 0; kk < BK; ++kk) {
            float af[8], bf[8];
            *(float4*)(af)     = *(const float4*)&As[kk][ty * 8];
            *(float4*)(af + 4) = *(const float4*)&As[kk][ty * 8 + 4];
            *(float4*)(bf)     = *(const float4*)&Bs[kk][tx * 8];
            *(float4*)(bf + 4) = *(const float4*)&Bs[kk][tx * 8 + 4];
#pragma unroll
            for (int i = 0; i < 8; ++i)
#pragma unroll
                for (int j = 0; j < 8; ++j)
                    acc[i][j] = fmaf(af[i], bf[j], acc[i][j]);
        }
    }

    int row0 = by * BM + ty * 8;
    int col0 = bx * BN + tx * 8;
#pragma unroll
    for (int i = 0; i < 8; ++i) {
        int r = row0 + i;
        if (EPI == 2) {
            int orow = win_row_to_orig(r);
            float* dst = Out + (size_t)orow * C_;
            const float* rs = Res + (size_t)orow * C_;
#pragma unroll
            for (int j = 0; j < 8; ++j) {
                int c = col0 + j;
                dst[c] = acc[i][j] + bias[c] + rs[c];
            }
        } else {
            float* dst = Out + (size_t)r * N;
#pragma unroll
            for (int j = 0; j < 8; ++j) {
                int c = col0 + j;
                float v = acc[i][j] + bias[c];
                if (EPI == 1) v = 0.5f * v * (1.f + erff(v * 0.70710678118654752f));
                if (EPI == 3) v += Res[(size_t)r * N + c];
                dst[c] = v;
            }
        }
    }
}

// ---------------- Attention: one block per (window, head) ----------------
__global__ __launch_bounds__(128) void attn_kernel(const float* __restrict__ rpb,
                                                   const float* __restrict__ mask)
{
    int bh = blockIdx.x;
    int bn = bh / NH_, head = bh - bn * NH_;
    int t = threadIdx.x;

    __shared__ float q [NTOK_][HD_];
    __shared__ float kk[NTOK_][HD_];
    __shared__ float vv[NTOK_][HD_];
    __shared__ float s [NTOK_][52];

    const float* base = g_qkv + (size_t)bn * NTOK_ * QKVN_ + head * HD_;
    for (int idx = t; idx < NTOK_ * HD_; idx += 128) {
        int n = idx >> 5, d = idx & 31;
        const float* p = base + (size_t)n * QKVN_ + d;
        q [n][d] = p[0]   * SCALE_;
        kk[n][d] = p[C_];
        vv[n][d] = p[2 * C_];
    }
    __syncthreads();

    int wi = bn & 63;
    const float* mrow = mask + (size_t)wi * NTOK_ * NTOK_;
    for (int idx = t; idx < NTOK_ * NTOK_; idx += 128) {
        int n = idx / NTOK_, m = idx - n * NTOK_;
        float acc = 0.f;
#pragma unroll
        for (int d = 0; d < HD_; ++d) acc = fmaf(q[n][d], kk[m][d], acc);
        int di = n / WS_ - m / WS_ + WS_ - 1;
        int dj = n % WS_ - m % WS_ + WS_ - 1;
        acc += rpb[(di * (2 * WS_ - 1) + dj) * NH_ + head] + mrow[idx];
        s[n][m] = acc;
    }
    __syncthreads();

    if (t < NTOK_) {
        float mx = -1e30f;
#pragma unroll 7
        for (int m = 0; m < NTOK_; ++m) mx = fmaxf(mx, s[t][m]);
        float sum = 0.f;
#pragma unroll 7
        for (int m = 0; m < NTOK_; ++m) { float e = __expf(s[t][m] - mx); s[t][m] = e; sum += e; }
        float inv = 1.f / sum;
#pragma unroll 7
        for (int m = 0; m < NTOK_; ++m) s[t][m] *= inv;
    }
    __syncthreads();

    for (int idx = t; idx < NTOK_ * HD_; idx += 128) {
        int n = idx >> 5, d = idx & 31;
        float acc = 0.f;
#pragma unroll 7
        for (int m = 0; m < NTOK_; ++m) acc = fmaf(s[n][m], vv[m][d], acc);
        g_att[((size_t)bn * NTOK_ + n) * C_ + head * HD_ + d] = acc;
    }
}

// ---------------- launch ----------------
extern "C" void kernel_launch(void* const* d_in, const int* in_sizes, int n_in,
                              void* d_out, int out_size)
{
    const float* x       = (const float*)d_in[0];
    const float* mask    = (const float*)d_in[1];
    const float* n1g     = (const float*)d_in[2];
    const float* n1b     = (const float*)d_in[3];
    const float* qkv_w   = (const float*)d_in[4];
    const float* qkv_b   = (const float*)d_in[5];
    const float* rpb     = (const float*)d_in[6];
    const float* proj_w  = (const float*)d_in[7];
    const float* proj_b  = (const float*)d_in[8];
    const float* n2g     = (const float*)d_in[9];
    const float* n2b     = (const float*)d_in[10];
    const float* fc1_w   = (const float*)d_in[11];
    const float* fc1_b   = (const float*)d_in[12];
    const float* fc2_w   = (const float*)d_in[13];
    const float* fc2_b   = (const float*)d_in[14];
    float* out = (float*)d_out;

    float *p_win, *p_qkv, *p_att, *p_x1, *p_h2, *p_hid;
    cudaGetSymbolAddress((void**)&p_win, g_win);
    cudaGetSymbolAddress((void**)&p_qkv, g_qkv);
    cudaGetSymbolAddress((void**)&p_att, g_att);
    cudaGetSymbolAddress((void**)&p_x1,  g_x1);
    cudaGetSymbolAddress((void**)&p_h2,  g_h2);
    cudaGetSymbolAddress((void**)&p_hid, g_hid);

    // 1) LN1 + roll + window partition
    ln_kernel<true><<<MTOT_, 128>>>(x, n1g, n1b, p_win);

    // 2) QKV GEMM: (100352,384) x (384,1152) + bias
    gemm_kernel<0><<<dim3(QKVN_ / BN, MTOT_ / BM), 256>>>(p_win, qkv_w, qkv_b, nullptr, p_qkv,
                                                          MTOT_, QKVN_, C_);

    // 3) windowed attention
    attn_kernel<<<BN_ * NH_, 128>>>(rpb, mask);

    // 4) proj GEMM + bias + window reverse + roll + residual -> g_x1 (orig order)
    gemm_kernel<2><<<dim3(C_ / BN, MTOT_ / BM), 256>>>(p_att, proj_w, proj_b, x, p_x1,
                                                       MTOT_, C_, C_);

    // 5) LN2
    ln_kernel<false><<<MTOT_, 128>>>(p_x1, n2g, n2b, p_h2);

    // 6) fc1 + GELU
    gemm_kernel<1><<<dim3(HID_ / BN, MTOT_ / BM), 256>>>(p_h2, fc1_w, fc1_b, nullptr, p_hid,
                                                         MTOT_, HID_, C_);

    // 7) fc2 + bias + residual -> out
    gemm_kernel<3><<<dim3(C_ / BN, MTOT_ / BM), 256>>>(p_hid, fc2_w, fc2_b, p_x1, out,
                                                       MTOT_, C_, HID_);
}

// round 3
// speedup vs baseline: 1.2528x; 1.2528x over previous
#include <cuda_runtime.h>
#include <cuda_bf16.h>
#include <math.h>
#include <stdint.h>

// ---------------- problem constants ----------------
#define B_      32
#define HW_     56
#define L_      3136
#define C_      384
#define NH_     12
#define HD_     32
#define WS_     7
#define NTOK_   49
#define NWIN_   64
#define BN_     2048
#define MTOT_   100352
#define HID_    1536
#define QKVN_   1152
#define SHIFT_  3
#define SCALE_  0.17677669529663687f

// ---------------- scratch ----------------
__device__ float g_win[(size_t)MTOT_ * C_];
__device__ float g_qkv[(size_t)MTOT_ * QKVN_];
__device__ float g_att[(size_t)MTOT_ * C_];
__device__ float g_x1 [(size_t)MTOT_ * C_];
__device__ float g_h2 [(size_t)MTOT_ * C_];
__device__ float g_hid[(size_t)MTOT_ * HID_];
// tf32-rounded weight copies (original [K,N] layout)
__device__ float g_wr_qkv[(size_t)C_ * QKVN_];
__device__ float g_wr_proj[(size_t)C_ * C_];
__device__ float g_wr_fc1[(size_t)C_ * HID_];
__device__ float g_wr_fc2[(size_t)HID_ * C_];

// ---------------- helpers ----------------
__device__ __forceinline__ float to_tf32(float x) {
    uint32_t u;
    asm("cvt.rna.tf32.f32 %0, %1;" : "=r"(u) : "f"(x));
    return __uint_as_float(u);
}

__device__ __forceinline__ void cp_async16(uint32_t saddr, const void* gptr) {
    asm volatile("cp.async.ca.shared.global [%0], [%1], 16;" :: "r"(saddr), "l"(gptr));
}
#define CP_COMMIT() asm volatile("cp.async.commit_group;" ::: "memory")
#define CP_WAIT(n)  asm volatile("cp.async.wait_group %0;" :: "n"(n) : "memory")

__device__ __forceinline__ void mma8(float* c, const uint32_t* a, const uint32_t* b) {
    asm volatile("mma.sync.aligned.m16n8k8.row.col.f32.tf32.tf32.f32 "
        "{%0,%1,%2,%3}, {%4,%5,%6,%7}, {%8,%9}, {%0,%1,%2,%3};"
        : "+f"(c[0]), "+f"(c[1]), "+f"(c[2]), "+f"(c[3])
        : "r"(a[0]), "r"(a[1]), "r"(a[2]), "r"(a[3]), "r"(b[0]), "r"(b[1]));
}

// ---------------- row map ----------------
__device__ __forceinline__ int win_row_to_orig(int r) {
    int bn = r / NTOK_, n = r - bn * NTOK_;
    int b  = bn >> 6,  wi = bn & 63;
    int i = n / WS_, j = n - i * WS_;
    int h = (wi >> 3) * WS_ + i + SHIFT_; if (h >= HW_) h -= HW_;
    int w = (wi & 7)  * WS_ + j + SHIFT_; if (w >= HW_) w -= HW_;
    return b * L_ + h * HW_ + w;
}

// ---------------- LayerNorm (outputs tf32-rounded) ----------------
template<bool SHIFT_WINDOW>
__global__ __launch_bounds__(128) void ln_kernel(const float* __restrict__ x,
                                                 const float* __restrict__ g,
                                                 const float* __restrict__ b,
                                                 float* __restrict__ out)
{
    int r = blockIdx.x;
    int src_row = SHIFT_WINDOW ? win_row_to_orig(r) : r;
    const float* src = x + (size_t)src_row * C_;
    int t = threadIdx.x;
    float v[3], s = 0.f, s2 = 0.f;
#pragma unroll
    for (int l = 0; l < 3; ++l) { v[l] = src[t + l * 128]; s += v[l]; s2 += v[l] * v[l]; }
    __shared__ float red[8];
#pragma unroll
    for (int o = 16; o > 0; o >>= 1) {
        s  += __shfl_down_sync(0xffffffffu, s,  o);
        s2 += __shfl_down_sync(0xffffffffu, s2, o);
    }
    int lane = t & 31, wid = t >> 5;
    if (lane == 0) { red[wid] = s; red[4 + wid] = s2; }
    __syncthreads();
    s  = red[0] + red[1] + red[2] + red[3];
    s2 = red[4] + red[5] + red[6] + red[7];
    float mean = s * (1.f / C_);
    float var  = s2 * (1.f / C_) - mean * mean;
    float inv  = rsqrtf(var + 1e-5f);
    float* dst = out + (size_t)r * C_;
#pragma unroll
    for (int l = 0; l < 3; ++l) {
        int c = t + l * 128;
        dst[c] = to_tf32((v[l] - mean) * inv * g[c] + b[c]);
    }
}

// ---------------- weight tf32 rounding (n divisible by 1024) ----------------
__global__ __launch_bounds__(256) void round_kernel(const float* __restrict__ src,
                                                    float* __restrict__ dst)
{
    int i = blockIdx.x * 256 + threadIdx.x;
    float4 v = ((const float4*)src)[i];
    v.x = to_tf32(v.x); v.y = to_tf32(v.y); v.z = to_tf32(v.z); v.w = to_tf32(v.w);
    ((float4*)dst)[i] = v;
}

// ---------------- tf32 mma.sync GEMM: Out[M,N] = A[M,K] @ W[K,N] ----------------
// EPI: 0=+bias ; 1=+bias,gelu,round ; 2=+bias,win-reverse+residual ; 3=+bias+residual
#define ASTR 20
#define BSTR 136

template<int EPI>
__global__ __launch_bounds__(256, 2) void mm_kernel(const float* __restrict__ A,
                                                    const float* __restrict__ W,
                                                    const float* __restrict__ bias,
                                                    const float* __restrict__ Res,
                                                    float* __restrict__ Out,
                                                    int K, int N)
{
    __shared__ float As[2][128 * ASTR];
    __shared__ float Bs[2][16 * BSTR];

    const int tid = threadIdx.x;
    const int w = tid >> 5, lane = tid & 31;
    const int warpM = w >> 1, warpN = w & 1;
    const int g = lane >> 2, tig = lane & 3;
    const int bx = blockIdx.x, by = blockIdx.y;

    const float* Ab = A + (size_t)by * 128 * K;
    const float* Wb = W + bx * 128;

    float acc[2][8][4];
#pragma unroll
    for (int mt = 0; mt < 2; ++mt)
#pragma unroll
        for (int nt = 0; nt < 8; ++nt)
#pragma unroll
            for (int i = 0; i < 4; ++i) acc[mt][nt][i] = 0.f;

    const int KT = K >> 4;

    // cp.async chunk mapping (per thread: 2 A-chunks + 2 B-chunks per stage)
    const int ca0 = tid, ca1 = tid + 256;
    uint32_t sA0 = (uint32_t)__cvta_generic_to_shared(&As[0][0]);
    uint32_t sB0 = (uint32_t)__cvta_generic_to_shared(&Bs[0][0]);

#define LOAD_STAGE(kt, buf) do {                                                   \
        int _k0 = (kt) << 4;                                                       \
        { int r = ca0 >> 2, sg = ca0 & 3;                                          \
          cp_async16(sA0 + (buf) * (128 * ASTR * 4) + (r * ASTR + sg * 4) * 4,     \
                     Ab + (size_t)r * K + _k0 + sg * 4); }                         \
        { int r = ca1 >> 2, sg = ca1 & 3;                                          \
          cp_async16(sA0 + (buf) * (128 * ASTR * 4) + (r * ASTR + sg * 4) * 4,     \
                     Ab + (size_t)r * K + _k0 + sg * 4); }                         \
        { int r = ca0 >> 5, sg = ca0 & 31;                                         \
          cp_async16(sB0 + (buf) * (16 * BSTR * 4) + (r * BSTR + sg * 4) * 4,      \
                     Wb + (size_t)(_k0 + r) * N + sg * 4); }                       \
        { int r = ca1 >> 5, sg = ca1 & 31;                                         \
          cp_async16(sB0 + (buf) * (16 * BSTR * 4) + (r * BSTR + sg * 4) * 4,      \
                     Wb + (size_t)(_k0 + r) * N + sg * 4); }                       \
        CP_COMMIT();                                                               \
    } while (0)

    LOAD_STAGE(0, 0);

    for (int kt = 0; kt < KT; ++kt) {
        int buf = kt & 1;
        if (kt + 1 < KT) {
            LOAD_STAGE(kt + 1, (kt + 1) & 1);
            CP_WAIT(1);
        } else {
            CP_WAIT(0);
        }
        __syncthreads();

        const uint32_t* Au = (const uint32_t*)As[buf];
        const uint32_t* Bu = (const uint32_t*)Bs[buf];
#pragma unroll
        for (int s = 0; s < 2; ++s) {
            uint32_t af[2][4], bf[8][2];
#pragma unroll
            for (int mt = 0; mt < 2; ++mt) {
                int r = warpM * 32 + mt * 16 + g;
                int c = s * 8 + tig;
                af[mt][0] = Au[r * ASTR + c];
                af[mt][1] = Au[(r + 8) * ASTR + c];
                af[mt][2] = Au[r * ASTR + c + 4];
                af[mt][3] = Au[(r + 8) * ASTR + c + 4];
            }
#pragma unroll
            for (int nt = 0; nt < 8; ++nt) {
                int cc = warpN * 64 + nt * 8 + g;
                int rr = s * 8 + tig;
                bf[nt][0] = Bu[rr * BSTR + cc];
                bf[nt][1] = Bu[(rr + 4) * BSTR + cc];
            }
#pragma unroll
            for (int mt = 0; mt < 2; ++mt)
#pragma unroll
                for (int nt = 0; nt < 8; ++nt)
                    mma8(acc[mt][nt], af[mt], bf[nt]);
        }
        __syncthreads();
    }

    // ---------------- epilogue ----------------
#pragma unroll
    for (int mt = 0; mt < 2; ++mt) {
#pragma unroll
        for (int rr = 0; rr < 2; ++rr) {
            int row = by * 128 + warpM * 32 + mt * 16 + g + rr * 8;
            if (EPI == 2) {
                int orow = win_row_to_orig(row);
                float* dst = Out + (size_t)orow * C_;
                const float* rs = Res + (size_t)orow * C_;
#pragma unroll
                for (int nt = 0; nt < 8; ++nt) {
                    int c = bx * 128 + warpN * 64 + nt * 8 + tig * 2;
                    dst[c]     = acc[mt][nt][rr * 2]     + bias[c]     + rs[c];
                    dst[c + 1] = acc[mt][nt][rr * 2 + 1] + bias[c + 1] + rs[c + 1];
                }
            } else {
                float* dst = Out + (size_t)row * N;
#pragma unroll
                for (int nt = 0; nt < 8; ++nt) {
                    int c = bx * 128 + warpN * 64 + nt * 8 + tig * 2;
                    float v0 = acc[mt][nt][rr * 2]     + bias[c];
                    float v1 = acc[mt][nt][rr * 2 + 1] + bias[c + 1];
                    if (EPI == 1) {
                        v0 = to_tf32(0.5f * v0 * (1.f + erff(v0 * 0.70710678118654752f)));
                        v1 = to_tf32(0.5f * v1 * (1.f + erff(v1 * 0.70710678118654752f)));
                    }
                    if (EPI == 3) {
                        v0 += Res[(size_t)row * N + c];
                        v1 += Res[(size_t)row * N + c + 1];
                    }
                    dst[c] = v0; dst[c + 1] = v1;
                }
            }
        }
    }
}

// ---------------- Attention (output tf32-rounded) ----------------
__global__ __launch_bounds__(128) void attn_kernel(const float* __restrict__ rpb,
                                                   const float* __restrict__ mask)
{
    int bh = blockIdx.x;
    int bn = bh / NH_, head = bh - bn * NH_;
    int t = threadIdx.x;

    __shared__ float q [NTOK_][HD_];
    __shared__ float kk[NTOK_][HD_];
    __shared__ float vv[NTOK_][HD_];
    __shared__ float s [NTOK_][52];

    const float* base = g_qkv + (size_t)bn * NTOK_ * QKVN_ + head * HD_;
    for (int idx = t; idx < NTOK_ * HD_; idx += 128) {
        int n = idx >> 5, d = idx & 31;
        const float* p = base + (size_t)n * QKVN_ + d;
        q [n][d] = p[0]   * SCALE_;
        kk[n][d] = p[C_];
        vv[n][d] = p[2 * C_];
    }
    __syncthreads();

    int wi = bn & 63;
    const float* mrow = mask + (size_t)wi * NTOK_ * NTOK_;
    for (int idx = t; idx < NTOK_ * NTOK_; idx += 128) {
        int n = idx / NTOK_, m = idx - n * NTOK_;
        float acc = 0.f;
#pragma unroll
        for (int d = 0; d < HD_; ++d) acc = fmaf(q[n][d], kk[m][d], acc);
        int di = n / WS_ - m / WS_ + WS_ - 1;
        int dj = n % WS_ - m % WS_ + WS_ - 1;
        acc += rpb[(di * (2 * WS_ - 1) + dj) * NH_ + head] + mrow[idx];
        s[n][m] = acc;
    }
    __syncthreads();

    if (t < NTOK_) {
        float mx = -1e30f;
#pragma unroll 7
        for (int m = 0; m < NTOK_; ++m) mx = fmaxf(mx, s[t][m]);
        float sum = 0.f;
#pragma unroll 7
        for (int m = 0; m < NTOK_; ++m) { float e = __expf(s[t][m] - mx); s[t][m] = e; sum += e; }
        float inv = 1.f / sum;
#pragma unroll 7
        for (int m = 0; m < NTOK_; ++m) s[t][m] *= inv;
    }
    __syncthreads();

    for (int idx = t; idx < NTOK_ * HD_; idx += 128) {
        int n = idx >> 5, d = idx & 31;
        float acc = 0.f;
#pragma unroll 7
        for (int m = 0; m < NTOK_; ++m) acc = fmaf(s[n][m], vv[m][d], acc);
        g_att[((size_t)bn * NTOK_ + n) * C_ + head * HD_ + d] = to_tf32(acc);
    }
}

// ---------------- launch ----------------
extern "C" void kernel_launch(void* const* d_in, const int* in_sizes, int n_in,
                              void* d_out, int out_size)
{
    const float* x       = (const float*)d_in[0];
    const float* mask    = (const float*)d_in[1];
    const float* n1g     = (const float*)d_in[2];
    const float* n1b     = (const float*)d_in[3];
    const float* qkv_w   = (const float*)d_in[4];
    const float* qkv_b   = (const float*)d_in[5];
    const float* rpb     = (const float*)d_in[6];
    const float* proj_w  = (const float*)d_in[7];
    const float* proj_b  = (const float*)d_in[8];
    const float* n2g     = (const float*)d_in[9];
    const float* n2b     = (const float*)d_in[10];
    const float* fc1_w   = (const float*)d_in[11];
    const float* fc1_b   = (const float*)d_in[12];
    const float* fc2_w   = (const float*)d_in[13];
    const float* fc2_b   = (const float*)d_in[14];
    float* out = (float*)d_out;

    float *p_win, *p_qkv, *p_att, *p_x1, *p_h2, *p_hid;
    float *pW_qkv, *pW_proj, *pW_fc1, *pW_fc2;
    cudaGetSymbolAddress((void**)&p_win, g_win);
    cudaGetSymbolAddress((void**)&p_qkv, g_qkv);
    cudaGetSymbolAddress((void**)&p_att, g_att);
    cudaGetSymbolAddress((void**)&p_x1,  g_x1);
    cudaGetSymbolAddress((void**)&p_h2,  g_h2);
    cudaGetSymbolAddress((void**)&p_hid, g_hid);
    cudaGetSymbolAddress((void**)&pW_qkv,  g_wr_qkv);
    cudaGetSymbolAddress((void**)&pW_proj, g_wr_proj);
    cudaGetSymbolAddress((void**)&pW_fc1,  g_wr_fc1);
    cudaGetSymbolAddress((void**)&pW_fc2,  g_wr_fc2);

    // 0) tf32-round weights (element counts all divisible by 1024)
    round_kernel<<<(C_ * QKVN_) / 1024, 256>>>(qkv_w, pW_qkv);
    round_kernel<<<(C_ * C_)    / 1024, 256>>>(proj_w, pW_proj);
    round_kernel<<<(C_ * HID_)  / 1024, 256>>>(fc1_w, pW_fc1);
    round_kernel<<<(HID_ * C_)  / 1024, 256>>>(fc2_w, pW_fc2);

    // 1) LN1 + roll + window partition (tf32-rounded)
    ln_kernel<true><<<MTOT_, 128>>>(x, n1g, n1b, p_win);

    // 2) QKV GEMM
    mm_kernel<0><<<dim3(QKVN_ / 128, MTOT_ / 128), 256>>>(p_win, pW_qkv, qkv_b, nullptr,
                                                          p_qkv, C_, QKVN_);
    // 3) windowed attention
    attn_kernel<<<BN_ * NH_, 128>>>(rpb, mask);

    // 4) proj + window reverse + residual
    mm_kernel<2><<<dim3(C_ / 128, MTOT_ / 128), 256>>>(p_att, pW_proj, proj_b, x,
                                                       p_x1, C_, C_);
    // 5) LN2 (tf32-rounded)
    ln_kernel<false><<<MTOT_, 128>>>(p_x1, n2g, n2b, p_h2);

    // 6) fc1 + GELU (tf32-rounded)
    mm_kernel<1><<<dim3(HID_ / 128, MTOT_ / 128), 256>>>(p_h2, pW_fc1, fc1_b, nullptr,
                                                         p_hid, C_, HID_);
    // 7) fc2 + residual -> out
    mm_kernel<3><<<dim3(C_ / 128, MTOT_ / 128), 256>>>(p_hid, pW_fc2, fc2_b, p_x1,
                                                       out, HID_, C_);
}

// round 4
// speedup vs baseline: 2.5297x; 2.0193x over previous
#include <cuda_runtime.h>
#include <cuda_fp16.h>
#include <math.h>
#include <stdint.h>

// ---------------- problem constants ----------------
#define B_      32
#define HW_     56
#define L_      3136
#define C_      384
#define NH_     12
#define HD_     32
#define WS_     7
#define NTOK_   49
#define NWIN_   64
#define BN_     2048
#define MTOT_   100352
#define HID_    1536
#define QKVN_   1152
#define SHIFT_  3
#define SCALE_  0.17677669529663687f

// ---------------- scratch ----------------
__device__ __half g_win[(size_t)MTOT_ * C_];      // LN1 windows (half)
__device__ float  g_qkv[(size_t)MTOT_ * QKVN_];   // qkv (float)
__device__ __half g_att[(size_t)MTOT_ * C_];      // attention out (half)
__device__ float  g_x1 [(size_t)MTOT_ * C_];      // residual1 (float)
__device__ __half g_h2 [(size_t)MTOT_ * C_];      // LN2 out (half)
__device__ __half g_hid[(size_t)MTOT_ * HID_];    // fc1+gelu (half)
// transposed half weights [N,K]
__device__ __half g_wh_qkv[(size_t)QKVN_ * C_];
__device__ __half g_wh_proj[(size_t)C_ * C_];
__device__ __half g_wh_fc1[(size_t)HID_ * C_];
__device__ __half g_wh_fc2[(size_t)C_ * HID_];

// ---------------- helpers ----------------
__device__ __forceinline__ void cp_async16(uint32_t saddr, const void* gptr) {
    asm volatile("cp.async.cg.shared.global [%0], [%1], 16;" :: "r"(saddr), "l"(gptr));
}
#define CP_COMMIT() asm volatile("cp.async.commit_group;" ::: "memory")
#define CP_WAIT(n)  asm volatile("cp.async.wait_group %0;" :: "n"(n) : "memory")

__device__ __forceinline__ void mma16816(float* c, const uint32_t* a, const uint32_t* b) {
    asm volatile("mma.sync.aligned.m16n8k16.row.col.f32.f16.f16.f32 "
        "{%0,%1,%2,%3}, {%4,%5,%6,%7}, {%8,%9}, {%0,%1,%2,%3};"
        : "+f"(c[0]), "+f"(c[1]), "+f"(c[2]), "+f"(c[3])
        : "r"(a[0]), "r"(a[1]), "r"(a[2]), "r"(a[3]), "r"(b[0]), "r"(b[1]));
}

// ---------------- row map ----------------
__device__ __forceinline__ int win_row_to_orig(int r) {
    int bn = r / NTOK_, n = r - bn * NTOK_;
    int b  = bn >> 6,  wi = bn & 63;
    int i = n / WS_, j = n - i * WS_;
    int h = (wi >> 3) * WS_ + i + SHIFT_; if (h >= HW_) h -= HW_;
    int w = (wi & 7)  * WS_ + j + SHIFT_; if (w >= HW_) w -= HW_;
    return b * L_ + h * HW_ + w;
}

// ---------------- LayerNorm (half output) ----------------
template<bool SHIFT_WINDOW>
__global__ __launch_bounds__(128) void ln_kernel(const float* __restrict__ x,
                                                 const float* __restrict__ g,
                                                 const float* __restrict__ b,
                                                 __half* __restrict__ out)
{
    int r = blockIdx.x;
    int src_row = SHIFT_WINDOW ? win_row_to_orig(r) : r;
    const float* src = x + (size_t)src_row * C_;
    int t = threadIdx.x;
    float v[3], s = 0.f, s2 = 0.f;
#pragma unroll
    for (int l = 0; l < 3; ++l) { v[l] = src[t + l * 128]; s += v[l]; s2 += v[l] * v[l]; }
    __shared__ float red[8];
#pragma unroll
    for (int o = 16; o > 0; o >>= 1) {
        s  += __shfl_down_sync(0xffffffffu, s,  o);
        s2 += __shfl_down_sync(0xffffffffu, s2, o);
    }
    int lane = t & 31, wid = t >> 5;
    if (lane == 0) { red[wid] = s; red[4 + wid] = s2; }
    __syncthreads();
    s  = red[0] + red[1] + red[2] + red[3];
    s2 = red[4] + red[5] + red[6] + red[7];
    float mean = s * (1.f / C_);
    float var  = s2 * (1.f / C_) - mean * mean;
    float inv  = rsqrtf(var + 1e-5f);
    __half* dst = out + (size_t)r * C_;
#pragma unroll
    for (int l = 0; l < 3; ++l) {
        int c = t + l * 128;
        dst[c] = __float2half((v[l] - mean) * inv * g[c] + b[c]);
    }
}

// ---------------- weight transpose+convert: dst[n][k] = half(src[k][n]) ----------------
__global__ __launch_bounds__(256) void transpose_half(const float* __restrict__ src,
                                                      __half* __restrict__ dst,
                                                      int K, int N)
{
    __shared__ float t[32][33];
    int bx = blockIdx.x * 32;  // n
    int by = blockIdx.y * 32;  // k
    int tx = threadIdx.x & 31, ty = threadIdx.x >> 5;
#pragma unroll
    for (int i = 0; i < 4; ++i)
        t[ty + i * 8][tx] = src[(size_t)(by + ty + i * 8) * N + bx + tx];
    __syncthreads();
#pragma unroll
    for (int i = 0; i < 4; ++i)
        dst[(size_t)(bx + ty + i * 8) * K + by + tx] = __float2half(t[tx][ty + i * 8]);
}

// ---------------- fp16 mma GEMM: Out[M,N] = A[M,K](h) @ Wt[N,K](h)^T ----------------
// EPI: 0=+bias->float ; 1=+bias,gelu->half ; 2=+bias,win-rev+residual->float ;
//      3=+bias+residual->float
#define ASTR 40   // halfs per row (20 b32)

template<int EPI>
__global__ __launch_bounds__(256, 2) void mm_kernel(const __half* __restrict__ A,
                                                    const __half* __restrict__ Wt,
                                                    const float* __restrict__ bias,
                                                    const float* __restrict__ Res,
                                                    void* __restrict__ OutV,
                                                    int K, int N)
{
    __shared__ __half As[2][128 * ASTR];
    __shared__ __half Bs[2][128 * ASTR];

    const int tid = threadIdx.x;
    const int w = tid >> 5, lane = tid & 31;
    const int warpM = w >> 1, warpN = w & 1;
    const int g = lane >> 2, tig = lane & 3;
    const int bx = blockIdx.x, by = blockIdx.y;

    const __half* Ab = A  + (size_t)by * 128 * K;
    const __half* Bb = Wt + (size_t)bx * 128 * K;

    float acc[2][8][4];
#pragma unroll
    for (int mt = 0; mt < 2; ++mt)
#pragma unroll
        for (int nt = 0; nt < 8; ++nt)
#pragma unroll
            for (int i = 0; i < 4; ++i) acc[mt][nt][i] = 0.f;

    const int KT = K >> 5;   // 32 halfs per stage
    const int ca0 = tid, ca1 = tid + 256;
    uint32_t sA0 = (uint32_t)__cvta_generic_to_shared(&As[0][0]);
    uint32_t sB0 = (uint32_t)__cvta_generic_to_shared(&Bs[0][0]);

#define LOAD_STAGE(kt, buf) do {                                                    \
        int _k0 = (kt) << 5;                                                        \
        { int r = ca0 >> 2, sg = ca0 & 3;                                           \
          cp_async16(sA0 + (buf) * (128 * ASTR * 2) + (r * ASTR + sg * 8) * 2,      \
                     Ab + (size_t)r * K + _k0 + sg * 8); }                          \
        { int r = ca1 >> 2, sg = ca1 & 3;                                           \
          cp_async16(sA0 + (buf) * (128 * ASTR * 2) + (r * ASTR + sg * 8) * 2,      \
                     Ab + (size_t)r * K + _k0 + sg * 8); }                          \
        { int r = ca0 >> 2, sg = ca0 & 3;                                           \
          cp_async16(sB0 + (buf) * (128 * ASTR * 2) + (r * ASTR + sg * 8) * 2,      \
                     Bb + (size_t)r * K + _k0 + sg * 8); }                          \
        { int r = ca1 >> 2, sg = ca1 & 3;                                           \
          cp_async16(sB0 + (buf) * (128 * ASTR * 2) + (r * ASTR + sg * 8) * 2,      \
                     Bb + (size_t)r * K + _k0 + sg * 8); }                          \
        CP_COMMIT();                                                                \
    } while (0)

    LOAD_STAGE(0, 0);

    for (int kt = 0; kt < KT; ++kt) {
        int buf = kt & 1;
        if (kt + 1 < KT) { LOAD_STAGE(kt + 1, (kt + 1) & 1); CP_WAIT(1); }
        else             { CP_WAIT(0); }
        __syncthreads();

        const uint32_t* Au = (const uint32_t*)As[buf];
        const uint32_t* Bu = (const uint32_t*)Bs[buf];
#pragma unroll
        for (int s = 0; s < 2; ++s) {
            uint32_t af[2][4], bf[8][2];
            int c2 = s * 8 + tig;
#pragma unroll
            for (int mt = 0; mt < 2; ++mt) {
                int r = warpM * 32 + mt * 16 + g;
                af[mt][0] = Au[r * 20 + c2];
                af[mt][1] = Au[(r + 8) * 20 + c2];
                af[mt][2] = Au[r * 20 + c2 + 4];
                af[mt][3] = Au[(r + 8) * 20 + c2 + 4];
            }
#pragma unroll
            for (int nt = 0; nt < 8; ++nt) {
                int n = warpN * 64 + nt * 8 + g;
                bf[nt][0] = Bu[n * 20 + c2];
                bf[nt][1] = Bu[n * 20 + c2 + 4];
            }
#pragma unroll
            for (int mt = 0; mt < 2; ++mt)
#pragma unroll
                for (int nt = 0; nt < 8; ++nt)
                    mma16816(acc[mt][nt], af[mt], bf[nt]);
        }
        __syncthreads();
    }

    // ---------------- epilogue ----------------
#pragma unroll
    for (int mt = 0; mt < 2; ++mt) {
#pragma unroll
        for (int rr = 0; rr < 2; ++rr) {
            int row = by * 128 + warpM * 32 + mt * 16 + g + rr * 8;
            if (EPI == 2) {
                int orow = win_row_to_orig(row);
                float* dst = (float*)OutV + (size_t)orow * C_;
                const float* rs = Res + (size_t)orow * C_;
#pragma unroll
                for (int nt = 0; nt < 8; ++nt) {
                    int c = bx * 128 + warpN * 64 + nt * 8 + tig * 2;
                    dst[c]     = acc[mt][nt][rr * 2]     + bias[c]     + rs[c];
                    dst[c + 1] = acc[mt][nt][rr * 2 + 1] + bias[c + 1] + rs[c + 1];
                }
            } else if (EPI == 1) {
                __half* dst = (__half*)OutV + (size_t)row * N;
#pragma unroll
                for (int nt = 0; nt < 8; ++nt) {
                    int c = bx * 128 + warpN * 64 + nt * 8 + tig * 2;
                    float v0 = acc[mt][nt][rr * 2]     + bias[c];
                    float v1 = acc[mt][nt][rr * 2 + 1] + bias[c + 1];
                    v0 = 0.5f * v0 * (1.f + erff(v0 * 0.70710678118654752f));
                    v1 = 0.5f * v1 * (1.f + erff(v1 * 0.70710678118654752f));
                    *(__half2*)(dst + c) = __halves2half2(__float2half(v0), __float2half(v1));
                }
            } else {
                float* dst = (float*)OutV + (size_t)row * N;
#pragma unroll
                for (int nt = 0; nt < 8; ++nt) {
                    int c = bx * 128 + warpN * 64 + nt * 8 + tig * 2;
                    float v0 = acc[mt][nt][rr * 2]     + bias[c];
                    float v1 = acc[mt][nt][rr * 2 + 1] + bias[c + 1];
                    if (EPI == 3) {
                        v0 += Res[(size_t)row * N + c];
                        v1 += Res[(size_t)row * N + c + 1];
                    }
                    dst[c] = v0; dst[c + 1] = v1;
                }
            }
        }
    }
}

// ---------------- Attention (half output) ----------------
__global__ __launch_bounds__(128) void attn_kernel(const float* __restrict__ rpb,
                                                   const float* __restrict__ mask)
{
    int bh = blockIdx.x;
    int bn = bh / NH_, head = bh - bn * NH_;
    int t = threadIdx.x;

    __shared__ float q [NTOK_][HD_];
    __shared__ float kk[NTOK_][HD_];
    __shared__ float vv[NTOK_][HD_];
    __shared__ float s [NTOK_][52];

    const float* base = g_qkv + (size_t)bn * NTOK_ * QKVN_ + head * HD_;
    for (int idx = t; idx < NTOK_ * HD_; idx += 128) {
        int n = idx >> 5, d = idx & 31;
        const float* p = base + (size_t)n * QKVN_ + d;
        q [n][d] = p[0]   * SCALE_;
        kk[n][d] = p[C_];
        vv[n][d] = p[2 * C_];
    }
    __syncthreads();

    int wi = bn & 63;
    const float* mrow = mask + (size_t)wi * NTOK_ * NTOK_;
    for (int idx = t; idx < NTOK_ * NTOK_; idx += 128) {
        int n = idx / NTOK_, m = idx - n * NTOK_;
        float acc = 0.f;
#pragma unroll
        for (int d = 0; d < HD_; ++d) acc = fmaf(q[n][d], kk[m][d], acc);
        int di = n / WS_ - m / WS_ + WS_ - 1;
        int dj = n % WS_ - m % WS_ + WS_ - 1;
        acc += rpb[(di * (2 * WS_ - 1) + dj) * NH_ + head] + mrow[idx];
        s[n][m] = acc;
    }
    __syncthreads();

    if (t < NTOK_) {
        float mx = -1e30f;
#pragma unroll 7
        for (int m = 0; m < NTOK_; ++m) mx = fmaxf(mx, s[t][m]);
        float sum = 0.f;
#pragma unroll 7
        for (int m = 0; m < NTOK_; ++m) { float e = __expf(s[t][m] - mx); s[t][m] = e; sum += e; }
        float inv = 1.f / sum;
#pragma unroll 7
        for (int m = 0; m < NTOK_; ++m) s[t][m] *= inv;
    }
    __syncthreads();

    for (int idx = t; idx < NTOK_ * HD_; idx += 128) {
        int n = idx >> 5, d = idx & 31;
        float acc = 0.f;
#pragma unroll 7
        for (int m = 0; m < NTOK_; ++m) acc = fmaf(s[n][m], vv[m][d], acc);
        g_att[((size_t)bn * NTOK_ + n) * C_ + head * HD_ + d] = __float2half(acc);
    }
}

// ---------------- launch ----------------
extern "C" void kernel_launch(void* const* d_in, const int* in_sizes, int n_in,
                              void* d_out, int out_size)
{
    const float* x       = (const float*)d_in[0];
    const float* mask    = (const float*)d_in[1];
    const float* n1g     = (const float*)d_in[2];
    const float* n1b     = (const float*)d_in[3];
    const float* qkv_w   = (const float*)d_in[4];
    const float* qkv_b   = (const float*)d_in[5];
    const float* rpb     = (const float*)d_in[6];
    const float* proj_w  = (const float*)d_in[7];
    const float* proj_b  = (const float*)d_in[8];
    const float* n2g     = (const float*)d_in[9];
    const float* n2b     = (const float*)d_in[10];
    const float* fc1_w   = (const float*)d_in[11];
    const float* fc1_b   = (const float*)d_in[12];
    const float* fc2_w   = (const float*)d_in[13];
    const float* fc2_b   = (const float*)d_in[14];
    float* out = (float*)d_out;

    __half *p_win, *p_att, *p_h2, *p_hid;
    float  *p_qkv, *p_x1;
    __half *pW_qkv, *pW_proj, *pW_fc1, *pW_fc2;
    cudaGetSymbolAddress((void**)&p_win, g_win);
    cudaGetSymbolAddress((void**)&p_qkv, g_qkv);
    cudaGetSymbolAddress((void**)&p_att, g_att);
    cudaGetSymbolAddress((void**)&p_x1,  g_x1);
    cudaGetSymbolAddress((void**)&p_h2,  g_h2);
    cudaGetSymbolAddress((void**)&p_hid, g_hid);
    cudaGetSymbolAddress((void**)&pW_qkv,  g_wh_qkv);
    cudaGetSymbolAddress((void**)&pW_proj, g_wh_proj);
    cudaGetSymbolAddress((void**)&pW_fc1,  g_wh_fc1);
    cudaGetSymbolAddress((void**)&pW_fc2,  g_wh_fc2);

    // 0) transpose + fp16-convert weights -> [N,K]
    transpose_half<<<dim3(QKVN_ / 32, C_ / 32), 256>>>(qkv_w, pW_qkv, C_, QKVN_);
    transpose_half<<<dim3(C_ / 32, C_ / 32), 256>>>(proj_w, pW_proj, C_, C_);
    transpose_half<<<dim3(HID_ / 32, C_ / 32), 256>>>(fc1_w, pW_fc1, C_, HID_);
    transpose_half<<<dim3(C_ / 32, HID_ / 32), 256>>>(fc2_w, pW_fc2, HID_, C_);

    // 1) LN1 + roll + window partition (half)
    ln_kernel<true><<<MTOT_, 128>>>(x, n1g, n1b, p_win);

    // 2) QKV GEMM -> float
    mm_kernel<0><<<dim3(QKVN_ / 128, MTOT_ / 128), 256>>>(p_win, pW_qkv, qkv_b, nullptr,
                                                          p_qkv, C_, QKVN_);
    // 3) windowed attention -> half
    attn_kernel<<<BN_ * NH_, 128>>>(rpb, mask);

    // 4) proj + window reverse + residual -> float (orig order)
    mm_kernel<2><<<dim3(C_ / 128, MTOT_ / 128), 256>>>(p_att, pW_proj, proj_b, x,
                                                       p_x1, C_, C_);
    // 5) LN2 -> half
    ln_kernel<false><<<MTOT_, 128>>>(p_x1, n2g, n2b, p_h2);

    // 6) fc1 + GELU -> half
    mm_kernel<1><<<dim3(HID_ / 128, MTOT_ / 128), 256>>>(p_h2, pW_fc1, fc1_b, nullptr,
                                                         p_hid, C_, HID_);
    // 7) fc2 + residual -> out (float)
    mm_kernel<3><<<dim3(C_ / 128, MTOT_ / 128), 256>>>(p_hid, pW_fc2, fc2_b, p_x1,
                                                       out, HID_, C_);
}